// round 3
// baseline (speedup 1.0000x reference)
#include <cuda_runtime.h>

// Problem dims (fixed by reference)
#define UDIM 400
#define VDIM 400
#define MDIM 4
#define VPAD (VDIM + 1)                     // duplicate column 0 at j=400 -> no j-wrap
#define NTEXP (MDIM * UDIM * VPAD)          // 641,600 padded texels

#define WARPS_PER_BLOCK 4
#define BLOCK_THREADS (WARPS_PER_BLOCK * 32)

// Packed table: per texel 12 floats = [W00..W22 (row-major 3x3), B0,B1,B2]
// 48 bytes per record, j-contiguous. A (j1, j1+1) pair is 96B contiguous.
__device__ __align__(16) float g_packed[(size_t)NTEXP * 12];

__global__ __launch_bounds__(256) void pack_kernel(
    const float* __restrict__ m_param,
    const float* __restrict__ b_param)
{
    int t = blockIdx.x * blockDim.x + threadIdx.x;
    if (t >= NTEXP) return;
    int m  = t / (UDIM * VPAD);
    int r  = t % (UDIM * VPAD);
    int i  = r / VPAD;
    int jp = r % VPAD;
    int j  = (jp == VDIM) ? 0 : jp;          // padded column duplicates j=0
    int src = (m * UDIM + i) * VDIM + j;

    const float* w = m_param + (size_t)src * 9;
    const float* b = b_param + (size_t)src * 3;
    float4 r0 = make_float4(w[0], w[1], w[2], w[3]);
    float4 r1 = make_float4(w[4], w[5], w[6], w[7]);
    float4 r2 = make_float4(w[8], b[0], b[1], b[2]);
    float4* dst = reinterpret_cast<float4*>(g_packed + (size_t)t * 12);
    dst[0] = r0; dst[1] = r1; dst[2] = r2;
}

__global__ __launch_bounds__(BLOCK_THREADS) void interp_kernel(
    const float* __restrict__ x,
    const int*   __restrict__ m,
    const float* __restrict__ u,
    const float* __restrict__ v,
    float* __restrict__ out,
    int N)
{
    // Staging: [warp][piece q][staggered point column] -> conflict-free LDS.128
    __shared__ float4 stage[WARPS_PER_BLOCK][12][32];
    __shared__ unsigned offs[WARPS_PER_BLOCK][64];   // per point: byte offsets of rowA, rowB

    const int warp = threadIdx.x >> 5;
    const int lane = threadIdx.x & 31;
    const int tid  = blockIdx.x * BLOCK_THREADS + threadIdx.x;
    const bool valid = (tid < N);
    const int t = valid ? tid : (N - 1);

    // ---- Phase A: per-lane index math (mirrors reference) ----
    float iu = u[t] * (float)UDIM;
    float iv = v[t] * (float)VDIM;
    if (iu == (float)UDIM) iu = (float)(UDIM - 1);
    if (iv == (float)VDIM) iv = (float)(VDIM - 1);

    float i1f = floorf(iu);
    float j1f = floorf(iv);
    int i1 = (int)i1f;
    int j1 = (int)j1f;                       // j2 = j1+1 via padded column
    int i2 = i1 + 1; if (i2 == UDIM) i2 = 0; // i wraps
    float ir = iu - i1f;
    float jr = iv - j1f;

    int mm = m[t];
    unsigned rowA = (unsigned)((mm * UDIM + i1) * VPAD + j1);
    unsigned rowB = (unsigned)((mm * UDIM + i2) * VPAD + j1);

    offs[warp][2 * lane + 0] = rowA * 48u;   // byte offset of 96B segment (i1, j1..j1+1)
    offs[warp][2 * lane + 1] = rowB * 48u;   // byte offset of 96B segment (i2, j1..j1+1)
    __syncwarp();

    // ---- Phase B: cooperative coalesced gather ----
    // 32 points x 12 float4 pieces = 384 loads = 12 rounds.
    // flat f = k*32 + lane -> point p = f/12, piece q = f%12.
    // Pieces 0..5 live in segment A (96B contiguous), 6..11 in segment B.
    const char* tb = (const char*)g_packed;
    #pragma unroll
    for (int k = 0; k < 12; k++) {
        int f = k * 32 + lane;
        int p = f / 12;
        int q = f - p * 12;
        int sel = (q >= 6) ? 1 : 0;
        int q6  = q - 6 * sel;
        unsigned off = offs[warp][2 * p + sel] + (unsigned)(q6 * 16);
        float4 val = __ldg(reinterpret_cast<const float4*>(tb + off));
        stage[warp][q][(p + q) & 31] = val;
    }
    __syncwarp();

    // ---- Phase C: per-lane blend + matvec ----
    float wgt0 = (1.0f - ir) * (1.0f - jr);  // (i1, j1)
    float wgt1 = (1.0f - ir) * jr;           // (i1, j1+1)
    float wgt2 = ir * (1.0f - jr);           // (i2, j1)
    float wgt3 = ir * jr;                    // (i2, j1+1)
    float wgt[4] = {wgt0, wgt1, wgt2, wgt3};

    float4 a0 = make_float4(0.f, 0.f, 0.f, 0.f);
    float4 a1 = make_float4(0.f, 0.f, 0.f, 0.f);
    float4 a2 = make_float4(0.f, 0.f, 0.f, 0.f);

    #pragma unroll
    for (int c = 0; c < 4; c++) {
        float wc = wgt[c];
        #pragma unroll
        for (int r = 0; r < 3; r++) {
            int q = c * 3 + r;
            float4 v4 = stage[warp][q][(lane + q) & 31];
            if (r == 0) {
                a0.x = fmaf(wc, v4.x, a0.x); a0.y = fmaf(wc, v4.y, a0.y);
                a0.z = fmaf(wc, v4.z, a0.z); a0.w = fmaf(wc, v4.w, a0.w);
            } else if (r == 1) {
                a1.x = fmaf(wc, v4.x, a1.x); a1.y = fmaf(wc, v4.y, a1.y);
                a1.z = fmaf(wc, v4.z, a1.z); a1.w = fmaf(wc, v4.w, a1.w);
            } else {
                a2.x = fmaf(wc, v4.x, a2.x); a2.y = fmaf(wc, v4.y, a2.y);
                a2.z = fmaf(wc, v4.z, a2.z); a2.w = fmaf(wc, v4.w, a2.w);
            }
        }
    }

    // packed order: [W00,W01,W02,W10] [W11,W12,W20,W21] [W22,B0,B1,B2]
    if (valid) {
        float x0 = x[3 * t + 0];
        float x1 = x[3 * t + 1];
        float x2 = x[3 * t + 2];
        // out_j = sum_i x_i * W[i][j] + B[j]
        out[3 * t + 0] = fmaf(x0, a0.x, fmaf(x1, a0.w, fmaf(x2, a1.z, a2.y)));
        out[3 * t + 1] = fmaf(x0, a0.y, fmaf(x1, a1.x, fmaf(x2, a1.w, a2.z)));
        out[3 * t + 2] = fmaf(x0, a0.z, fmaf(x1, a1.y, fmaf(x2, a2.x, a2.w)));
    }
}

extern "C" void kernel_launch(void* const* d_in, const int* in_sizes, int n_in,
                              void* d_out, int out_size) {
    const float* x       = (const float*)d_in[0];   // [N,3]
    const int*   m       = (const int*)  d_in[1];   // [N]
    const float* u       = (const float*)d_in[2];   // [N]
    const float* v       = (const float*)d_in[3];   // [N]
    const float* m_param = (const float*)d_in[4];   // [M,U*V,3,3]
    const float* b_param = (const float*)d_in[5];   // [M,U*V,1,3]
    float* out = (float*)d_out;

    int N = in_sizes[1];  // element count of m

    // Stage 1: repack table (with duplicated j=0 column) into 48B records
    {
        int threads = 256;
        int blocks = (NTEXP + threads - 1) / threads;
        pack_kernel<<<blocks, threads>>>(m_param, b_param);
    }
    // Stage 2: warp-cooperative gather + interp + matvec
    {
        int blocks = (N + BLOCK_THREADS - 1) / BLOCK_THREADS;
        interp_kernel<<<blocks, BLOCK_THREADS>>>(x, m, u, v, out, N);
    }
}

// round 4
// speedup vs baseline: 1.4435x; 1.4435x over previous
#include <cuda_runtime.h>
#include <cuda_fp16.h>

// Problem dims (fixed by reference)
#define UDIM 400
#define VDIM 400
#define MDIM 4
#define NTEX (MDIM * UDIM * VDIM)   // 640,000 blocks

// 2x2-block table: per texel (m,i,j) one 96B record holding all 4 bilinear
// corners in fp16: corner c (c = i_sel*2 + j_sel) occupies halves 12c..12c+11
// as [W00..W22 row-major, B0,B1,B2]. Wraps baked in at pack time.
// 96B record = 6 uint4, 32B-aligned (stride 96) -> exactly 3 L2 sectors.
__device__ uint4 g_blk[(size_t)NTEX * 6];

__global__ __launch_bounds__(256) void pack_kernel(
    const float* __restrict__ m_param,
    const float* __restrict__ b_param)
{
    int t = blockIdx.x * blockDim.x + threadIdx.x;
    if (t >= NTEX) return;
    int m = t / (UDIM * VDIM);
    int r = t % (UDIM * VDIM);
    int i = r / VDIM;
    int j = r % VDIM;
    int i2 = i + 1; if (i2 == UDIM) i2 = 0;
    int j2 = j + 1; if (j2 == VDIM) j2 = 0;

    int src[4];
    src[0] = (m * UDIM + i ) * VDIM + j;    // (i1, j1)
    src[1] = (m * UDIM + i ) * VDIM + j2;   // (i1, j2)
    src[2] = (m * UDIM + i2) * VDIM + j;    // (i2, j1)
    src[3] = (m * UDIM + i2) * VDIM + j2;   // (i2, j2)

    __align__(16) __half h[48];
    #pragma unroll
    for (int c = 0; c < 4; c++) {
        const float* w = m_param + (size_t)src[c] * 9;
        const float* b = b_param + (size_t)src[c] * 3;
        #pragma unroll
        for (int k = 0; k < 9; k++) h[c * 12 + k] = __float2half_rn(w[k]);
        #pragma unroll
        for (int k = 0; k < 3; k++) h[c * 12 + 9 + k] = __float2half_rn(b[k]);
    }

    uint4* dst = g_blk + (size_t)t * 6;
    const uint4* s = reinterpret_cast<const uint4*>(h);
    #pragma unroll
    for (int k = 0; k < 6; k++) dst[k] = s[k];
}

__global__ __launch_bounds__(256) void interp_kernel(
    const float* __restrict__ x,
    const int*   __restrict__ m,
    const float* __restrict__ u,
    const float* __restrict__ v,
    float* __restrict__ out,
    int N)
{
    int tid = blockIdx.x * blockDim.x + threadIdx.x;
    if (tid >= N) return;

    // --- index math (mirrors reference exactly) ---
    float iu = u[tid] * (float)UDIM;
    float iv = v[tid] * (float)VDIM;
    if (iu == (float)UDIM) iu = (float)(UDIM - 1);
    if (iv == (float)VDIM) iv = (float)(VDIM - 1);

    float i1f = floorf(iu);
    float j1f = floorf(iv);
    int i1 = (int)i1f;
    int j1 = (int)j1f;
    float ir = iu - i1f;
    float jr = iv - j1f;

    int mm = m[tid];
    int blk = (mm * UDIM + i1) * VDIM + j1;

    // weights, corner order c = i_sel*2 + j_sel
    float w0 = (1.0f - ir) * (1.0f - jr);   // (i1, j1)
    float w1 = (1.0f - ir) * jr;            // (i1, j2)
    float w2 = ir * (1.0f - jr);            // (i2, j1)
    float w3 = ir * jr;                     // (i2, j2)

    // --- one 96B block read: 6x LDG.128 ---
    const uint4* p = g_blk + (size_t)blk * 6;
    uint4 q0 = __ldg(p + 0);
    uint4 q1 = __ldg(p + 1);
    uint4 q2 = __ldg(p + 2);
    uint4 q3 = __ldg(p + 3);
    uint4 q4 = __ldg(p + 4);
    uint4 q5 = __ldg(p + 5);

    unsigned uu[24] = { q0.x, q0.y, q0.z, q0.w,  q1.x, q1.y, q1.z, q1.w,
                        q2.x, q2.y, q2.z, q2.w,  q3.x, q3.y, q3.z, q3.w,
                        q4.x, q4.y, q4.z, q4.w,  q5.x, q5.y, q5.z, q5.w };

    // blend 4 corners in fp32; corner c = half2 slots 6c..6c+5
    float2 acc[6];
    #pragma unroll
    for (int s = 0; s < 6; s++) acc[s] = make_float2(0.f, 0.f);

    float wgt[4] = { w0, w1, w2, w3 };
    #pragma unroll
    for (int c = 0; c < 4; c++) {
        float wc = wgt[c];
        #pragma unroll
        for (int s = 0; s < 6; s++) {
            __half2 hv = *reinterpret_cast<const __half2*>(&uu[c * 6 + s]);
            float2 f = __half22float2(hv);
            acc[s].x = fmaf(wc, f.x, acc[s].x);
            acc[s].y = fmaf(wc, f.y, acc[s].y);
        }
    }
    // acc layout: [0]=(W00,W01) [1]=(W02,W10) [2]=(W11,W12)
    //             [3]=(W20,W21) [4]=(W22,B0)  [5]=(B1,B2)

    float x0 = x[3 * tid + 0];
    float x1 = x[3 * tid + 1];
    float x2 = x[3 * tid + 2];

    // out_j = sum_i x_i * W[i][j] + B[j]
    out[3 * tid + 0] = fmaf(x0, acc[0].x, fmaf(x1, acc[1].y, fmaf(x2, acc[3].x, acc[4].y)));
    out[3 * tid + 1] = fmaf(x0, acc[0].y, fmaf(x1, acc[2].x, fmaf(x2, acc[3].y, acc[5].x)));
    out[3 * tid + 2] = fmaf(x0, acc[1].x, fmaf(x1, acc[2].y, fmaf(x2, acc[4].x, acc[5].y)));
}

extern "C" void kernel_launch(void* const* d_in, const int* in_sizes, int n_in,
                              void* d_out, int out_size) {
    const float* x       = (const float*)d_in[0];   // [N,3]
    const int*   m       = (const int*)  d_in[1];   // [N]
    const float* u       = (const float*)d_in[2];   // [N]
    const float* v       = (const float*)d_in[3];   // [N]
    const float* m_param = (const float*)d_in[4];   // [M,U*V,3,3]
    const float* b_param = (const float*)d_in[5];   // [M,U*V,1,3]
    float* out = (float*)d_out;

    int N = in_sizes[1];  // element count of m

    // Stage 1: build fp16 2x2-block table (wraps baked in)
    {
        int threads = 256;
        int blocks = (NTEX + threads - 1) / threads;
        pack_kernel<<<blocks, threads>>>(m_param, b_param);
    }
    // Stage 2: one-block gather + blend + matvec per point
    {
        int threads = 256;
        int blocks = (N + threads - 1) / threads;
        interp_kernel<<<blocks, threads>>>(x, m, u, v, out, N);
    }
}

// round 5
// speedup vs baseline: 1.4906x; 1.0327x over previous
#include <cuda_runtime.h>
#include <cuda_fp16.h>

// Problem dims (fixed by reference)
#define UDIM 400
#define VDIM 400
#define MDIM 4
#define NTEX (MDIM * UDIM * VDIM)   // 640,000 blocks

// 2x2-block table: per texel (m,i,j) one 96B record holding all 4 bilinear
// corners in fp16: corner c (c = i_sel*2 + j_sel) occupies halves 12c..12c+11
// as [W00..W22 row-major, B0,B1,B2]. Wraps baked in at pack time.
// 96B record, 32B-aligned (stride 96, base align 32) -> three 256-bit loads.
__device__ __align__(32) uint4 g_blk[(size_t)NTEX * 6];

// ---------------- pack: tile-through-shared ----------------
#define TI 16
#define TJ 16
#define HALO_TEX ((TI + 1) * (TJ + 1))      // 289 texels incl. wrap halo

__global__ __launch_bounds__(256) void pack_kernel(
    const float* __restrict__ m_param,
    const float* __restrict__ b_param)
{
    __shared__ __half sh[HALO_TEX * 12];    // [texel][12] fp16

    const int tid = threadIdx.x;
    const int mm = blockIdx.z;
    const int i0 = blockIdx.y * TI;
    const int j0 = blockIdx.x * TJ;

    // Load W halo: 289 * 9 floats, flat & coalesced within row segments
    for (int idx = tid; idx < HALO_TEX * 9; idx += 256) {
        int tex = idx / 9;
        int k   = idx - tex * 9;
        int il  = tex / (TJ + 1);
        int jl  = tex - il * (TJ + 1);
        int gi = i0 + il; if (gi == UDIM) gi = 0;
        int gj = j0 + jl; if (gj == VDIM) gj = 0;
        float val = m_param[((size_t)(mm * UDIM + gi) * VDIM + gj) * 9 + k];
        sh[tex * 12 + k] = __float2half_rn(val);
    }
    // Load B halo: 289 * 3 floats
    for (int idx = tid; idx < HALO_TEX * 3; idx += 256) {
        int tex = idx / 3;
        int k   = idx - tex * 3;
        int il  = tex / (TJ + 1);
        int jl  = tex - il * (TJ + 1);
        int gi = i0 + il; if (gi == UDIM) gi = 0;
        int gj = j0 + jl; if (gj == VDIM) gj = 0;
        float val = b_param[((size_t)(mm * UDIM + gi) * VDIM + gj) * 3 + k];
        sh[tex * 12 + 9 + k] = __float2half_rn(val);
    }
    __syncthreads();

    // Assemble: each thread owns one block record (il, jl)
    int il = tid / TJ;
    int jl = tid - il * TJ;
    // corner texel indices in halo tile (c = i_sel*2 + j_sel)
    int t00 = (il    ) * (TJ + 1) + jl;
    int t01 = (il    ) * (TJ + 1) + jl + 1;
    int t10 = (il + 1) * (TJ + 1) + jl;
    int t11 = (il + 1) * (TJ + 1) + jl + 1;
    int ctex[4] = { t00, t01, t10, t11 };

    unsigned rec[24];
    #pragma unroll
    for (int c = 0; c < 4; c++) {
        const unsigned* s = reinterpret_cast<const unsigned*>(sh + ctex[c] * 12);
        #pragma unroll
        for (int k = 0; k < 6; k++) rec[c * 6 + k] = s[k];
    }

    size_t blk = (size_t)(mm * UDIM + (i0 + il)) * VDIM + (j0 + jl);
    uint4* dst = g_blk + blk * 6;
    #pragma unroll
    for (int k = 0; k < 6; k++)
        dst[k] = make_uint4(rec[4*k], rec[4*k+1], rec[4*k+2], rec[4*k+3]);
}

// ---------------- interp ----------------
__device__ __forceinline__ void ldg256(const void* p, unsigned r[8]) {
    asm("ld.global.nc.v8.b32 {%0,%1,%2,%3,%4,%5,%6,%7}, [%8];"
        : "=r"(r[0]), "=r"(r[1]), "=r"(r[2]), "=r"(r[3]),
          "=r"(r[4]), "=r"(r[5]), "=r"(r[6]), "=r"(r[7])
        : "l"(p));
}

__global__ __launch_bounds__(256) void interp_kernel(
    const float* __restrict__ x,
    const int*   __restrict__ m,
    const float* __restrict__ u,
    const float* __restrict__ v,
    float* __restrict__ out,
    int N)
{
    int tid = blockIdx.x * blockDim.x + threadIdx.x;
    if (tid >= N) return;

    // --- index math (mirrors reference exactly) ---
    float iu = u[tid] * (float)UDIM;
    float iv = v[tid] * (float)VDIM;
    if (iu == (float)UDIM) iu = (float)(UDIM - 1);
    if (iv == (float)VDIM) iv = (float)(VDIM - 1);

    float i1f = floorf(iu);
    float j1f = floorf(iv);
    int i1 = (int)i1f;
    int j1 = (int)j1f;
    float ir = iu - i1f;
    float jr = iv - j1f;

    int mm = m[tid];
    size_t blk = (size_t)(mm * UDIM + i1) * VDIM + j1;

    // weights, corner order c = i_sel*2 + j_sel
    float wgt[4];
    wgt[0] = (1.0f - ir) * (1.0f - jr);   // (i1, j1)
    wgt[1] = (1.0f - ir) * jr;            // (i1, j2)
    wgt[2] = ir * (1.0f - jr);            // (i2, j1)
    wgt[3] = ir * jr;                     // (i2, j2)

    // --- one 96B block read: 3x LDG.256 ---
    const char* p = reinterpret_cast<const char*>(g_blk) + blk * 96;
    unsigned uu[24];
    ldg256(p,      uu +  0);
    ldg256(p + 32, uu +  8);
    ldg256(p + 64, uu + 16);

    // blend 4 corners in fp32; corner c = half2 slots 6c..6c+5
    float2 acc[6];
    #pragma unroll
    for (int s = 0; s < 6; s++) acc[s] = make_float2(0.f, 0.f);

    #pragma unroll
    for (int c = 0; c < 4; c++) {
        float wc = wgt[c];
        #pragma unroll
        for (int s = 0; s < 6; s++) {
            __half2 hv = *reinterpret_cast<const __half2*>(&uu[c * 6 + s]);
            float2 f = __half22float2(hv);
            acc[s].x = fmaf(wc, f.x, acc[s].x);
            acc[s].y = fmaf(wc, f.y, acc[s].y);
        }
    }
    // acc layout: [0]=(W00,W01) [1]=(W02,W10) [2]=(W11,W12)
    //             [3]=(W20,W21) [4]=(W22,B0)  [5]=(B1,B2)

    float x0 = x[3 * tid + 0];
    float x1 = x[3 * tid + 1];
    float x2 = x[3 * tid + 2];

    // out_j = sum_i x_i * W[i][j] + B[j]
    out[3 * tid + 0] = fmaf(x0, acc[0].x, fmaf(x1, acc[1].y, fmaf(x2, acc[3].x, acc[4].y)));
    out[3 * tid + 1] = fmaf(x0, acc[0].y, fmaf(x1, acc[2].x, fmaf(x2, acc[3].y, acc[5].x)));
    out[3 * tid + 2] = fmaf(x0, acc[1].x, fmaf(x1, acc[2].y, fmaf(x2, acc[4].x, acc[5].y)));
}

extern "C" void kernel_launch(void* const* d_in, const int* in_sizes, int n_in,
                              void* d_out, int out_size) {
    const float* x       = (const float*)d_in[0];   // [N,3]
    const int*   m       = (const int*)  d_in[1];   // [N]
    const float* u       = (const float*)d_in[2];   // [N]
    const float* v       = (const float*)d_in[3];   // [N]
    const float* m_param = (const float*)d_in[4];   // [M,U*V,3,3]
    const float* b_param = (const float*)d_in[5];   // [M,U*V,1,3]
    float* out = (float*)d_out;

    int N = in_sizes[1];  // element count of m

    // Stage 1: build fp16 2x2-block table (wraps baked in), tiled through smem
    {
        dim3 grid(VDIM / TJ, UDIM / TI, MDIM);   // 25 x 25 x 4
        pack_kernel<<<grid, 256>>>(m_param, b_param);
    }
    // Stage 2: one-block gather (3x 256-bit loads) + blend + matvec per point
    {
        int threads = 256;
        int blocks = (N + threads - 1) / threads;
        interp_kernel<<<blocks, threads>>>(x, m, u, v, out, N);
    }
}

// round 6
// speedup vs baseline: 1.6668x; 1.1182x over previous
#include <cuda_runtime.h>
#include <cuda_fp16.h>

// Problem dims (fixed by reference)
#define UDIM 400
#define VDIM 400
#define MDIM 4
#define VPAD (VDIM + 1)                    // duplicate column 0 at j=400 -> no j-wrap
#define NTEXP (MDIM * UDIM * VPAD)         // 641,600 padded texels

// Compact fp16 table: per texel one 32B record (16 halves):
// [W00..W22 row-major (9), B0,B1,B2 (3), pad (4)].
// j-contiguous with VPAD -> a (j, j+1) pair is 64B contiguous, 32B-aligned.
// Total 20.5 MB -> L2-resident.
__device__ __align__(32) unsigned g_tbl[(size_t)NTEXP * 8];

__global__ __launch_bounds__(256) void pack_kernel(
    const float* __restrict__ m_param,
    const float* __restrict__ b_param)
{
    int t = blockIdx.x * blockDim.x + threadIdx.x;
    if (t >= NTEXP) return;
    int m  = t / (UDIM * VPAD);
    int r  = t % (UDIM * VPAD);
    int i  = r / VPAD;
    int jp = r % VPAD;
    int j  = (jp == VDIM) ? 0 : jp;         // padded column duplicates j=0
    size_t src = (size_t)(m * UDIM + i) * VDIM + j;

    const float* w = m_param + src * 9;
    const float* b = b_param + src * 3;

    __align__(32) __half h[16];
    #pragma unroll
    for (int k = 0; k < 9; k++) h[k] = __float2half_rn(w[k]);
    #pragma unroll
    for (int k = 0; k < 3; k++) h[9 + k] = __float2half_rn(b[k]);
    h[12] = h[13] = h[14] = h[15] = __half(0.0f);

    const uint4* s = reinterpret_cast<const uint4*>(h);
    uint4* dst = reinterpret_cast<uint4*>(g_tbl + (size_t)t * 8);
    dst[0] = s[0];
    dst[1] = s[1];
}

__device__ __forceinline__ void ldg256(const void* p, unsigned r[8]) {
    asm("ld.global.nc.v8.b32 {%0,%1,%2,%3,%4,%5,%6,%7}, [%8];"
        : "=r"(r[0]), "=r"(r[1]), "=r"(r[2]), "=r"(r[3]),
          "=r"(r[4]), "=r"(r[5]), "=r"(r[6]), "=r"(r[7])
        : "l"(p));
}

__global__ __launch_bounds__(256) void interp_kernel(
    const float* __restrict__ x,
    const int*   __restrict__ m,
    const float* __restrict__ u,
    const float* __restrict__ v,
    float* __restrict__ out,
    int N)
{
    int tid = blockIdx.x * blockDim.x + threadIdx.x;
    if (tid >= N) return;

    // --- index math (mirrors reference exactly) ---
    float iu = u[tid] * (float)UDIM;
    float iv = v[tid] * (float)VDIM;
    if (iu == (float)UDIM) iu = (float)(UDIM - 1);
    if (iv == (float)VDIM) iv = (float)(VDIM - 1);

    float i1f = floorf(iu);
    float j1f = floorf(iv);
    int i1 = (int)i1f;
    int j1 = (int)j1f;                       // j2 via padded column
    int i2 = i1 + 1; if (i2 == UDIM) i2 = 0; // i wraps
    float ir = iu - i1f;
    float jr = iv - j1f;

    int mm = m[tid];
    size_t rowA = (size_t)(mm * UDIM + i1) * VPAD + j1;
    size_t rowB = (size_t)(mm * UDIM + i2) * VPAD + j1;

    // Issue both 64B row-pair reads up front (4x LDG.256, 2 base addresses)
    const char* base = reinterpret_cast<const char*>(g_tbl);
    unsigned a1[8], a2[8], b1[8], b2[8];
    ldg256(base + rowA * 32,      a1);   // (i1, j1)
    ldg256(base + rowA * 32 + 32, a2);   // (i1, j1+1)
    ldg256(base + rowB * 32,      b1);   // (i2, j1)
    ldg256(base + rowB * 32 + 32, b2);   // (i2, j1+1)

    float wA1 = (1.0f - ir) * (1.0f - jr);
    float wA2 = (1.0f - ir) * jr;
    float wB1 = ir * (1.0f - jr);
    float wB2 = ir * jr;

    // blend in fp32; record half2 slots s=0..5:
    // [0]=(W00,W01) [1]=(W02,W10) [2]=(W11,W12) [3]=(W20,W21) [4]=(W22,B0) [5]=(B1,B2)
    float2 acc[6];
    #pragma unroll
    for (int s = 0; s < 6; s++) {
        __half2 hA1 = *reinterpret_cast<const __half2*>(&a1[s]);
        __half2 hA2 = *reinterpret_cast<const __half2*>(&a2[s]);
        __half2 hB1 = *reinterpret_cast<const __half2*>(&b1[s]);
        __half2 hB2 = *reinterpret_cast<const __half2*>(&b2[s]);
        float2 fA1 = __half22float2(hA1);
        float2 fA2 = __half22float2(hA2);
        float2 fB1 = __half22float2(hB1);
        float2 fB2 = __half22float2(hB2);
        acc[s].x = fmaf(wA1, fA1.x, fmaf(wA2, fA2.x, fmaf(wB1, fB1.x, wB2 * fB2.x)));
        acc[s].y = fmaf(wA1, fA1.y, fmaf(wA2, fA2.y, fmaf(wB1, fB1.y, wB2 * fB2.y)));
    }

    float x0 = x[3 * tid + 0];
    float x1 = x[3 * tid + 1];
    float x2 = x[3 * tid + 2];

    // out_j = sum_i x_i * W[i][j] + B[j]
    out[3 * tid + 0] = fmaf(x0, acc[0].x, fmaf(x1, acc[1].y, fmaf(x2, acc[3].x, acc[4].y)));
    out[3 * tid + 1] = fmaf(x0, acc[0].y, fmaf(x1, acc[2].x, fmaf(x2, acc[3].y, acc[5].x)));
    out[3 * tid + 2] = fmaf(x0, acc[1].x, fmaf(x1, acc[2].y, fmaf(x2, acc[4].x, acc[5].y)));
}

extern "C" void kernel_launch(void* const* d_in, const int* in_sizes, int n_in,
                              void* d_out, int out_size) {
    const float* x       = (const float*)d_in[0];   // [N,3]
    const int*   m       = (const int*)  d_in[1];   // [N]
    const float* u       = (const float*)d_in[2];   // [N]
    const float* v       = (const float*)d_in[3];   // [N]
    const float* m_param = (const float*)d_in[4];   // [M,U*V,3,3]
    const float* b_param = (const float*)d_in[5];   // [M,U*V,1,3]
    float* out = (float*)d_out;

    int N = in_sizes[1];  // element count of m

    // Stage 1: streaming convert to compact fp16 records (20.5 MB, L2-resident)
    {
        int threads = 256;
        int blocks = (NTEXP + threads - 1) / threads;
        pack_kernel<<<blocks, threads>>>(m_param, b_param);
    }
    // Stage 2: gather (4x LDG.256) + blend + matvec per point
    {
        int threads = 256;
        int blocks = (N + threads - 1) / threads;
        interp_kernel<<<blocks, threads>>>(x, m, u, v, out, N);
    }
}